// round 4
// baseline (speedup 1.0000x reference)
#include <cuda_runtime.h>
#include <stdint.h>

#define N_NODES 10000
#define N_EDGES 80000
#define E_TOT   (N_EDGES + N_NODES)   // self-loops appended
#define IN_DIM  768
#define HID     512
#define HEADS   4
#define C1      (HEADS * HID)         // 2048
#define OUT_DIM 768

// ---------------- scratch (static device memory, no allocs) ----------------
__device__ float g_h1[N_NODES * C1];        // x @ W1
__device__ float g_out1[N_NODES * C1];      // layer1 aggregated + elu
__device__ float g_h2[N_NODES * OUT_DIM];   // act1 @ W2
__device__ float g_as1[N_NODES * HEADS];
__device__ float g_ad1[N_NODES * HEADS];
__device__ float g_emax1[N_NODES * HEADS];
__device__ float g_den1[N_NODES * HEADS];
__device__ float g_ex1[(size_t)E_TOT * HEADS];
__device__ float g_as2[N_NODES];
__device__ float g_ad2[N_NODES];
__device__ float g_emax2[N_NODES];
__device__ float g_den2[N_NODES];
__device__ float g_ex2[E_TOT];

// ================= TF32x3 tensor-core GEMM, cp.async double-buffered =======
// C[M,N] = A[M,K] @ B[K,N] row-major. Block 128x128x32, 256 thr, warp 64x32.
#define BM 128
#define BN 128
#define BK 32
#define APAD 36    // 32+4,  conflict-free a-frag loads, 16B-aligned rows
#define BPAD 136   // 128+8, conflict-free b-frag loads, 16B-aligned rows

__device__ __forceinline__ uint32_t f2tf32(float x) {
    uint32_t u;
    asm("cvt.rna.tf32.f32 %0, %1;" : "=r"(u) : "f"(x));
    return u;
}

__device__ __forceinline__ void mma_tf32(float c[4],
                                         const uint32_t a[4],
                                         const uint32_t b[2]) {
    asm volatile(
        "mma.sync.aligned.m16n8k8.row.col.f32.tf32.tf32.f32 "
        "{%0,%1,%2,%3},{%4,%5,%6,%7},{%8,%9},{%0,%1,%2,%3};"
        : "+f"(c[0]), "+f"(c[1]), "+f"(c[2]), "+f"(c[3])
        : "r"(a[0]), "r"(a[1]), "r"(a[2]), "r"(a[3]), "r"(b[0]), "r"(b[1]));
}

__device__ __forceinline__ void cp16(float* smem_dst, const float* gmem_src) {
    uint32_t s = (uint32_t)__cvta_generic_to_shared(smem_dst);
    asm volatile("cp.async.cg.shared.global [%0], [%1], 16;" :: "r"(s), "l"(gmem_src));
}
__device__ __forceinline__ void cp16_zero(float* smem_dst, const float* gmem_src) {
    uint32_t s = (uint32_t)__cvta_generic_to_shared(smem_dst);
    asm volatile("cp.async.cg.shared.global [%0], [%1], 16, 0;" :: "r"(s), "l"(gmem_src));
}

__device__ __forceinline__ void split(float v, uint32_t& hi, uint32_t& lo) {
    hi = f2tf32(v);
    lo = f2tf32(v - __uint_as_float(hi));
}

__global__ void __launch_bounds__(256)
gemm_tf32x3(int M, int N, int K,
            const float* __restrict__ A,
            const float* __restrict__ B,
            float* __restrict__ C) {
    extern __shared__ float smem[];
    float* As[2] = { smem, smem + BM * APAD };                 // [BM][APAD]
    float* Bs[2] = { smem + 2 * BM * APAD,
                     smem + 2 * BM * APAD + BK * BPAD };        // [BK][BPAD]

    const int tid  = threadIdx.x;
    const int lane = tid & 31;
    const int wid  = tid >> 5;
    const int warp_m = (wid >> 2) * 64;
    const int warp_n = (wid & 3) * 32;
    const int brow = blockIdx.y * BM;
    const int bcol = blockIdx.x * BN;

    // per-thread load coords (4 float4 each for A and B)
    const int ar = tid >> 1;                 // rows 0..127 (2 thr/row, 2 f4 each... )
    // A: linear p*256+tid ; r = >>3, kv = (&7)*4
    // B: k = >>5, nv = (&31)*4

    float acc[4][4][4];
#pragma unroll
    for (int mt = 0; mt < 4; mt++)
#pragma unroll
        for (int nt = 0; nt < 4; nt++)
#pragma unroll
            for (int r = 0; r < 4; r++) acc[mt][nt][r] = 0.f;
    (void)ar;

    const int T = K / BK;

    auto load_tile = [&](int it, int buf) {
        int k0 = it * BK;
#pragma unroll
        for (int p = 0; p < 4; p++) {
            int linear = p * 256 + tid;
            int r  = linear >> 3;
            int kv = (linear & 7) * 4;
            const float* src = A + (size_t)(brow + r) * K + k0 + kv;
            float* dst = As[buf] + r * APAD + kv;
            if (brow + r < M) cp16(dst, src);
            else              cp16_zero(dst, A);   // zero-fill, no read
        }
#pragma unroll
        for (int p = 0; p < 4; p++) {
            int linear = p * 256 + tid;
            int k  = linear >> 5;
            int nv = (linear & 31) * 4;
            cp16(Bs[buf] + k * BPAD + nv, B + (size_t)(k0 + k) * N + bcol + nv);
        }
        asm volatile("cp.async.commit_group;");
    };

    load_tile(0, 0);

    for (int it = 0; it < T; it++) {
        const int buf = it & 1;
        asm volatile("cp.async.wait_group 0;");
        __syncthreads();
        if (it + 1 < T) load_tile(it + 1, buf ^ 1);

        const float* sa = As[buf];
        const float* sb = Bs[buf];
#pragma unroll
        for (int ks = 0; ks < BK / 8; ks++) {
            const int kk = ks * 8 + (lane & 3);
            uint32_t ah[4][4], al[4][4], bh[4][2], bl[4][2];
#pragma unroll
            for (int mt = 0; mt < 4; mt++) {
                int r = warp_m + mt * 16 + (lane >> 2);
                split(sa[r * APAD + kk],           ah[mt][0], al[mt][0]);
                split(sa[(r + 8) * APAD + kk],     ah[mt][1], al[mt][1]);
                split(sa[r * APAD + kk + 4],       ah[mt][2], al[mt][2]);
                split(sa[(r + 8) * APAD + kk + 4], ah[mt][3], al[mt][3]);
            }
#pragma unroll
            for (int nt = 0; nt < 4; nt++) {
                int n = warp_n + nt * 8 + (lane >> 2);
                split(sb[kk * BPAD + n],       bh[nt][0], bl[nt][0]);
                split(sb[(kk + 4) * BPAD + n], bh[nt][1], bl[nt][1]);
            }
#pragma unroll
            for (int mt = 0; mt < 4; mt++)
#pragma unroll
                for (int nt = 0; nt < 4; nt++) mma_tf32(acc[mt][nt], ah[mt], bh[nt]);
#pragma unroll
            for (int mt = 0; mt < 4; mt++)
#pragma unroll
                for (int nt = 0; nt < 4; nt++) mma_tf32(acc[mt][nt], ah[mt], bl[nt]);
#pragma unroll
            for (int mt = 0; mt < 4; mt++)
#pragma unroll
                for (int nt = 0; nt < 4; nt++) mma_tf32(acc[mt][nt], al[mt], bh[nt]);
        }
        __syncthreads();
    }

    // ---- epilogue ----
#pragma unroll
    for (int mt = 0; mt < 4; mt++) {
        int r0 = brow + warp_m + mt * 16 + (lane >> 2);
#pragma unroll
        for (int nt = 0; nt < 4; nt++) {
            int cc = bcol + warp_n + nt * 8 + (lane & 3) * 2;
            if (r0 < M)
                *(float2*)&C[(size_t)r0 * N + cc] =
                    make_float2(acc[mt][nt][0], acc[mt][nt][1]);
            if (r0 + 8 < M)
                *(float2*)&C[(size_t)(r0 + 8) * N + cc] =
                    make_float2(acc[mt][nt][2], acc[mt][nt][3]);
        }
    }
}

#define GEMM_SMEM ((2 * BM * APAD + 2 * BK * BPAD) * 4)

// ----------------- per-node attention coefficients -------------------------
__global__ void attn_coef(const float* __restrict__ h,
                          const float* __restrict__ a_src,
                          const float* __restrict__ a_dst,
                          float* __restrict__ as_out,
                          float* __restrict__ ad_out,
                          int H, int D) {
    int n = blockIdx.x;
    int w = threadIdx.x >> 5;
    int lane = threadIdx.x & 31;
    const float* hp  = h + (size_t)n * H * D + (size_t)w * D;
    const float* ap  = a_src + (size_t)w * D;
    const float* bp  = a_dst + (size_t)w * D;
    float s = 0.f, d = 0.f;
    for (int i = lane; i < D; i += 32) {
        float v = hp[i];
        s += v * ap[i];
        d += v * bp[i];
    }
#pragma unroll
    for (int off = 16; off; off >>= 1) {
        s += __shfl_down_sync(0xffffffffu, s, off);
        d += __shfl_down_sync(0xffffffffu, d, off);
    }
    if (lane == 0) {
        as_out[(size_t)n * H + w] = s;
        ad_out[(size_t)n * H + w] = d;
    }
}

// ----------------- softmax init --------------------------------------------
__global__ void init_softmax(float* __restrict__ emax, float* __restrict__ den, int n) {
    int i = blockIdx.x * blockDim.x + threadIdx.x;
    if (i < n) {
        emax[i] = __int_as_float(0xff800000u);  // -inf
        den[i]  = 0.f;
    }
}

__device__ __forceinline__ void atomicMaxFloat(float* addr, float val) {
    if (val >= 0.f)
        atomicMax((int*)addr, __float_as_int(val));
    else
        atomicMin((unsigned int*)addr, __float_as_uint(val));
}

// edge_index is int32 in practice (JAX x64 disabled). [2,E] row-major.
__device__ __forceinline__ void edge_ends(const int* __restrict__ ei,
                                          int e, int E, int& src, int& dst) {
    if (e < E) {
        src = min(max(ei[e], 0), N_NODES - 1);
        dst = min(max(ei[E + e], 0), N_NODES - 1);
    } else {
        src = dst = e - E;  // self loop
    }
}

__global__ void edge_max(const int* __restrict__ ei, int E, int Etot, int H,
                         const float* __restrict__ asn, const float* __restrict__ adn,
                         float* __restrict__ emax) {
    int idx = blockIdx.x * blockDim.x + threadIdx.x;
    if (idx >= Etot * H) return;
    int e = idx / H, hh = idx - e * H;
    int src, dst;
    edge_ends(ei, e, E, src, dst);
    float v = asn[(size_t)src * H + hh] + adn[(size_t)dst * H + hh];
    v = v > 0.f ? v : 0.2f * v;
    atomicMaxFloat(&emax[(size_t)dst * H + hh], v);
}

__global__ void edge_exp(const int* __restrict__ ei, int E, int Etot, int H,
                         const float* __restrict__ asn, const float* __restrict__ adn,
                         const float* __restrict__ emax,
                         float* __restrict__ ex, float* __restrict__ den) {
    int idx = blockIdx.x * blockDim.x + threadIdx.x;
    if (idx >= Etot * H) return;
    int e = idx / H, hh = idx - e * H;
    int src, dst;
    edge_ends(ei, e, E, src, dst);
    float v = asn[(size_t)src * H + hh] + adn[(size_t)dst * H + hh];
    v = v > 0.f ? v : 0.2f * v;
    float xv = __expf(v - emax[(size_t)dst * H + hh]);
    ex[idx] = xv;
    atomicAdd(&den[(size_t)dst * H + hh], xv);
}

__global__ void aggregate(const int* __restrict__ ei, int E,
                          const float* __restrict__ h,
                          const float* __restrict__ ex,
                          const float* __restrict__ den,
                          float* __restrict__ out, int H, int Dh) {
    int e = blockIdx.x;
    int src, dst;
    edge_ends(ei, e, E, src, dst);
    int cols = H * Dh;
    int d = threadIdx.x * 4;
    int hh = d / Dh;
    float alpha = ex[(size_t)e * H + hh] / (den[(size_t)dst * H + hh] + 1e-16f);
    float4 v = *(const float4*)(h + (size_t)src * cols + d);
    float* o = out + (size_t)dst * cols + d;
    atomicAdd(o + 0, alpha * v.x);
    atomicAdd(o + 1, alpha * v.y);
    atomicAdd(o + 2, alpha * v.z);
    atomicAdd(o + 3, alpha * v.w);
}

__global__ void elu_bias(float* __restrict__ x, const float* __restrict__ b,
                         int n, int cols) {
    int i = blockIdx.x * blockDim.x + threadIdx.x;
    if (i >= n) return;
    float v = x[i] + b[i % cols];
    x[i] = v > 0.f ? v : expm1f(v);
}

__global__ void add_bias(float* __restrict__ x, const float* __restrict__ b,
                         int n, int cols) {
    int i = blockIdx.x * blockDim.x + threadIdx.x;
    if (i >= n) return;
    x[i] += b[i % cols];
}

// ---------------------------------------------------------------------------
extern "C" void kernel_launch(void* const* d_in, const int* in_sizes, int n_in,
                              void* d_out, int out_size) {
    const float* x   = (const float*)d_in[0];
    const int*   ei  = (const int*)d_in[1];     // int32 (JAX x64 disabled)
    const float* W1  = (const float*)d_in[2];
    const float* a1s = (const float*)d_in[3];
    const float* a1d = (const float*)d_in[4];
    const float* b1  = (const float*)d_in[5];
    const float* W2  = (const float*)d_in[6];
    const float* a2s = (const float*)d_in[7];
    const float* a2d = (const float*)d_in[8];
    const float* b2  = (const float*)d_in[9];
    float*       out = (float*)d_out;

    float *h1, *out1, *h2, *as1, *ad1, *em1, *dn1, *ex1;
    float *as2, *ad2, *em2, *dn2, *ex2;
    cudaGetSymbolAddress((void**)&h1,  g_h1);
    cudaGetSymbolAddress((void**)&out1, g_out1);
    cudaGetSymbolAddress((void**)&h2,  g_h2);
    cudaGetSymbolAddress((void**)&as1, g_as1);
    cudaGetSymbolAddress((void**)&ad1, g_ad1);
    cudaGetSymbolAddress((void**)&em1, g_emax1);
    cudaGetSymbolAddress((void**)&dn1, g_den1);
    cudaGetSymbolAddress((void**)&ex1, g_ex1);
    cudaGetSymbolAddress((void**)&as2, g_as2);
    cudaGetSymbolAddress((void**)&ad2, g_ad2);
    cudaGetSymbolAddress((void**)&em2, g_emax2);
    cudaGetSymbolAddress((void**)&dn2, g_den2);
    cudaGetSymbolAddress((void**)&ex2, g_ex2);

    cudaFuncSetAttribute(gemm_tf32x3,
                         cudaFuncAttributeMaxDynamicSharedMemorySize, GEMM_SMEM);

    // ---------------- layer 1 ----------------
    {
        dim3 grid(C1 / 128, (N_NODES + 127) / 128);
        gemm_tf32x3<<<grid, 256, GEMM_SMEM>>>(N_NODES, C1, IN_DIM, x, W1, h1);
    }
    attn_coef<<<N_NODES, 32 * HEADS>>>(h1, a1s, a1d, as1, ad1, HEADS, HID);

    int tot1 = N_NODES * HEADS;
    init_softmax<<<(tot1 + 255) / 256, 256>>>(em1, dn1, tot1);
    cudaMemsetAsync(out1, 0, sizeof(float) * (size_t)N_NODES * C1);

    int et1 = E_TOT * HEADS;
    edge_max<<<(et1 + 255) / 256, 256>>>(ei, N_EDGES, E_TOT, HEADS, as1, ad1, em1);
    edge_exp<<<(et1 + 255) / 256, 256>>>(ei, N_EDGES, E_TOT, HEADS, as1, ad1, em1, ex1, dn1);
    aggregate<<<E_TOT, C1 / 4>>>(ei, N_EDGES, h1, ex1, dn1, out1, HEADS, HID);

    int n1 = N_NODES * C1;
    elu_bias<<<(n1 + 255) / 256, 256>>>(out1, b1, n1, C1);

    // ---------------- layer 2 ----------------
    {
        dim3 grid(OUT_DIM / 128, (N_NODES + 127) / 128);
        gemm_tf32x3<<<grid, 256, GEMM_SMEM>>>(N_NODES, OUT_DIM, C1, out1, W2, h2);
    }
    attn_coef<<<N_NODES, 32>>>(h2, a2s, a2d, as2, ad2, 1, OUT_DIM);

    init_softmax<<<(N_NODES + 255) / 256, 256>>>(em2, dn2, N_NODES);
    cudaMemsetAsync(out, 0, sizeof(float) * (size_t)N_NODES * OUT_DIM);

    edge_max<<<(E_TOT + 255) / 256, 256>>>(ei, N_EDGES, E_TOT, 1, as2, ad2, em2);
    edge_exp<<<(E_TOT + 255) / 256, 256>>>(ei, N_EDGES, E_TOT, 1, as2, ad2, em2, ex2, dn2);
    aggregate<<<E_TOT, OUT_DIM / 4>>>(ei, N_EDGES, h2, ex2, dn2, out, 1, OUT_DIM);

    int n2 = N_NODES * OUT_DIM;
    add_bias<<<(n2 + 255) / 256, 256>>>(out, b2, n2, OUT_DIM);
}

// round 5
// speedup vs baseline: 1.1204x; 1.1204x over previous
#include <cuda_runtime.h>
#include <stdint.h>

#define N_NODES 10000
#define N_EDGES 80000
#define E_TOT   (N_EDGES + N_NODES)   // self-loops appended
#define IN_DIM  768
#define HID     512
#define HEADS   4
#define C1      (HEADS * HID)         // 2048
#define OUT_DIM 768

// ---------------- scratch (static device memory, no allocs) ----------------
__device__ float g_h1[N_NODES * C1];        // x @ W1
__device__ float g_out1[N_NODES * C1];      // layer1 aggregated + elu
__device__ float g_h2[N_NODES * OUT_DIM];   // act1 @ W2
__device__ float g_as1[N_NODES * HEADS];
__device__ float g_ad1[N_NODES * HEADS];
__device__ float g_emax1[N_NODES * HEADS];
__device__ float g_den1[N_NODES * HEADS];
__device__ float g_ex1[(size_t)E_TOT * HEADS];
__device__ float g_as2[N_NODES];
__device__ float g_ad2[N_NODES];
__device__ float g_emax2[N_NODES];
__device__ float g_den2[N_NODES];
__device__ float g_ex2[E_TOT];

// ================= TF32x3 tensor-core GEMM, register-prefetched ============
// C[M,N] = A[M,K] @ B[K,N] row-major. Block 128x128x32, 256 thr, warp 64x32.
// Split (hi/lo tf32) done ONCE per element at STS time; LDG latency hidden by
// prefetching the next raw tile into registers while computing the current.
#define BM 128
#define BN 128
#define BK 32
#define APAD 36    // 32+4  -> conflict-free a-frag loads
#define BPAD 136   // 128+8 -> conflict-free b-frag loads

__device__ __forceinline__ uint32_t f2tf32(float x) {
    uint32_t u;
    asm("cvt.rna.tf32.f32 %0, %1;" : "=r"(u) : "f"(x));
    return u;
}

__device__ __forceinline__ void mma_tf32(float c[4],
                                         const uint32_t a[4],
                                         const uint32_t b[2]) {
    asm volatile(
        "mma.sync.aligned.m16n8k8.row.col.f32.tf32.tf32.f32 "
        "{%0,%1,%2,%3},{%4,%5,%6,%7},{%8,%9},{%0,%1,%2,%3};"
        : "+f"(c[0]), "+f"(c[1]), "+f"(c[2]), "+f"(c[3])
        : "r"(a[0]), "r"(a[1]), "r"(a[2]), "r"(a[3]), "r"(b[0]), "r"(b[1]));
}

__device__ __forceinline__ void split_store(float* hi_p, float* lo_p, float4 v) {
    uint32_t hx = f2tf32(v.x), hy = f2tf32(v.y), hz = f2tf32(v.z), hw = f2tf32(v.w);
    float4 hi = make_float4(__uint_as_float(hx), __uint_as_float(hy),
                            __uint_as_float(hz), __uint_as_float(hw));
    float4 lo = make_float4(v.x - hi.x, v.y - hi.y, v.z - hi.z, v.w - hi.w);
    *(float4*)hi_p = hi;
    *(float4*)lo_p = lo;
}

__global__ void __launch_bounds__(256)
gemm_tf32x3(int M, int N, int K,
            const float* __restrict__ A,
            const float* __restrict__ B,
            float* __restrict__ C) {
    extern __shared__ float smem[];
    float* As_hi = smem;                        // [BM][APAD]
    float* As_lo = As_hi + BM * APAD;
    float* Bs_hi = As_lo + BM * APAD;           // [BK][BPAD]
    float* Bs_lo = Bs_hi + BK * BPAD;

    const int tid  = threadIdx.x;
    const int lane = tid & 31;
    const int wid  = tid >> 5;
    const int warp_m = (wid >> 2) * 64;
    const int warp_n = (wid & 3) * 32;
    const int brow = blockIdx.y * BM;
    const int bcol = blockIdx.x * BN;

    float acc[4][4][4];
#pragma unroll
    for (int mt = 0; mt < 4; mt++)
#pragma unroll
        for (int nt = 0; nt < 4; nt++)
#pragma unroll
            for (int r = 0; r < 4; r++) acc[mt][nt][r] = 0.f;

    const uint32_t* uAh = (const uint32_t*)As_hi;
    const uint32_t* uAl = (const uint32_t*)As_lo;
    const uint32_t* uBh = (const uint32_t*)Bs_hi;
    const uint32_t* uBl = (const uint32_t*)Bs_lo;

    // per-thread raw-tile registers (4 float4 A + 4 float4 B)
    float4 ra[4], rb[4];

    auto ldg_tile = [&](int it) {
        const int k0 = it * BK;
#pragma unroll
        for (int p = 0; p < 4; p++) {
            int linear = p * 256 + tid;
            int r  = linear >> 3;
            int kv = (linear & 7) * 4;
            ra[p] = (brow + r < M)
                ? *(const float4*)(A + (size_t)(brow + r) * K + k0 + kv)
                : make_float4(0.f, 0.f, 0.f, 0.f);
        }
#pragma unroll
        for (int p = 0; p < 4; p++) {
            int linear = p * 256 + tid;
            int k  = linear >> 5;
            int nv = (linear & 31) * 4;
            rb[p] = *(const float4*)(B + (size_t)(k0 + k) * N + bcol + nv);
        }
    };

    auto sts_tile = [&]() {
#pragma unroll
        for (int p = 0; p < 4; p++) {
            int linear = p * 256 + tid;
            int r  = linear >> 3;
            int kv = (linear & 7) * 4;
            split_store(As_hi + r * APAD + kv, As_lo + r * APAD + kv, ra[p]);
        }
#pragma unroll
        for (int p = 0; p < 4; p++) {
            int linear = p * 256 + tid;
            int k  = linear >> 5;
            int nv = (linear & 31) * 4;
            split_store(Bs_hi + k * BPAD + nv, Bs_lo + k * BPAD + nv, rb[p]);
        }
    };

    const int T = K / BK;
    ldg_tile(0);
    sts_tile();
    __syncthreads();

    for (int it = 0; it < T; it++) {
        if (it + 1 < T) ldg_tile(it + 1);   // latency hidden behind compute

#pragma unroll
        for (int ks = 0; ks < BK / 8; ks++) {
            uint32_t ah[4][4], al[4][4], bh[4][2], bl[4][2];
            const int kk = ks * 8 + (lane & 3);
#pragma unroll
            for (int mt = 0; mt < 4; mt++) {
                int r = warp_m + mt * 16 + (lane >> 2);
                ah[mt][0] = uAh[r * APAD + kk];
                ah[mt][1] = uAh[(r + 8) * APAD + kk];
                ah[mt][2] = uAh[r * APAD + kk + 4];
                ah[mt][3] = uAh[(r + 8) * APAD + kk + 4];
                al[mt][0] = uAl[r * APAD + kk];
                al[mt][1] = uAl[(r + 8) * APAD + kk];
                al[mt][2] = uAl[r * APAD + kk + 4];
                al[mt][3] = uAl[(r + 8) * APAD + kk + 4];
            }
#pragma unroll
            for (int nt = 0; nt < 4; nt++) {
                int n = warp_n + nt * 8 + (lane >> 2);
                bh[nt][0] = uBh[kk * BPAD + n];
                bh[nt][1] = uBh[(kk + 4) * BPAD + n];
                bl[nt][0] = uBl[kk * BPAD + n];
                bl[nt][1] = uBl[(kk + 4) * BPAD + n];
            }
#pragma unroll
            for (int mt = 0; mt < 4; mt++)
#pragma unroll
                for (int nt = 0; nt < 4; nt++) mma_tf32(acc[mt][nt], ah[mt], bh[nt]);
#pragma unroll
            for (int mt = 0; mt < 4; mt++)
#pragma unroll
                for (int nt = 0; nt < 4; nt++) mma_tf32(acc[mt][nt], ah[mt], bl[nt]);
#pragma unroll
            for (int mt = 0; mt < 4; mt++)
#pragma unroll
                for (int nt = 0; nt < 4; nt++) mma_tf32(acc[mt][nt], al[mt], bh[nt]);
        }
        __syncthreads();
        if (it + 1 < T) {
            sts_tile();
            __syncthreads();
        }
    }

    // ---- epilogue ----
#pragma unroll
    for (int mt = 0; mt < 4; mt++) {
        int r0 = brow + warp_m + mt * 16 + (lane >> 2);
#pragma unroll
        for (int nt = 0; nt < 4; nt++) {
            int cc = bcol + warp_n + nt * 8 + (lane & 3) * 2;
            if (r0 < M)
                *(float2*)&C[(size_t)r0 * N + cc] =
                    make_float2(acc[mt][nt][0], acc[mt][nt][1]);
            if (r0 + 8 < M)
                *(float2*)&C[(size_t)(r0 + 8) * N + cc] =
                    make_float2(acc[mt][nt][2], acc[mt][nt][3]);
        }
    }
}

#define GEMM_SMEM ((2 * BM * APAD + 2 * BK * BPAD) * 4)

// ----------------- per-node attention coefficients -------------------------
__global__ void attn_coef(const float* __restrict__ h,
                          const float* __restrict__ a_src,
                          const float* __restrict__ a_dst,
                          float* __restrict__ as_out,
                          float* __restrict__ ad_out,
                          int H, int D) {
    int n = blockIdx.x;
    int w = threadIdx.x >> 5;
    int lane = threadIdx.x & 31;
    const float* hp  = h + (size_t)n * H * D + (size_t)w * D;
    const float* ap  = a_src + (size_t)w * D;
    const float* bp  = a_dst + (size_t)w * D;
    float s = 0.f, d = 0.f;
    for (int i = lane; i < D; i += 32) {
        float v = hp[i];
        s += v * ap[i];
        d += v * bp[i];
    }
#pragma unroll
    for (int off = 16; off; off >>= 1) {
        s += __shfl_down_sync(0xffffffffu, s, off);
        d += __shfl_down_sync(0xffffffffu, d, off);
    }
    if (lane == 0) {
        as_out[(size_t)n * H + w] = s;
        ad_out[(size_t)n * H + w] = d;
    }
}

// ----------------- softmax init --------------------------------------------
__global__ void init_softmax(float* __restrict__ emax, float* __restrict__ den, int n) {
    int i = blockIdx.x * blockDim.x + threadIdx.x;
    if (i < n) {
        emax[i] = __int_as_float(0xff800000u);  // -inf
        den[i]  = 0.f;
    }
}

__device__ __forceinline__ void atomicMaxFloat(float* addr, float val) {
    if (val >= 0.f)
        atomicMax((int*)addr, __float_as_int(val));
    else
        atomicMin((unsigned int*)addr, __float_as_uint(val));
}

// edge_index is int32 in practice (JAX x64 disabled). [2,E] row-major.
__device__ __forceinline__ void edge_ends(const int* __restrict__ ei,
                                          int e, int E, int& src, int& dst) {
    if (e < E) {
        src = min(max(ei[e], 0), N_NODES - 1);
        dst = min(max(ei[E + e], 0), N_NODES - 1);
    } else {
        src = dst = e - E;  // self loop
    }
}

__global__ void edge_max(const int* __restrict__ ei, int E, int Etot, int H,
                         const float* __restrict__ asn, const float* __restrict__ adn,
                         float* __restrict__ emax) {
    int idx = blockIdx.x * blockDim.x + threadIdx.x;
    if (idx >= Etot * H) return;
    int e = idx / H, hh = idx - e * H;
    int src, dst;
    edge_ends(ei, e, E, src, dst);
    float v = asn[(size_t)src * H + hh] + adn[(size_t)dst * H + hh];
    v = v > 0.f ? v : 0.2f * v;
    atomicMaxFloat(&emax[(size_t)dst * H + hh], v);
}

__global__ void edge_exp(const int* __restrict__ ei, int E, int Etot, int H,
                         const float* __restrict__ asn, const float* __restrict__ adn,
                         const float* __restrict__ emax,
                         float* __restrict__ ex, float* __restrict__ den) {
    int idx = blockIdx.x * blockDim.x + threadIdx.x;
    if (idx >= Etot * H) return;
    int e = idx / H, hh = idx - e * H;
    int src, dst;
    edge_ends(ei, e, E, src, dst);
    float v = asn[(size_t)src * H + hh] + adn[(size_t)dst * H + hh];
    v = v > 0.f ? v : 0.2f * v;
    float xv = __expf(v - emax[(size_t)dst * H + hh]);
    ex[idx] = xv;
    atomicAdd(&den[(size_t)dst * H + hh], xv);
}

__global__ void aggregate(const int* __restrict__ ei, int E,
                          const float* __restrict__ h,
                          const float* __restrict__ ex,
                          const float* __restrict__ den,
                          float* __restrict__ out, int H, int Dh) {
    int e = blockIdx.x;
    int src, dst;
    edge_ends(ei, e, E, src, dst);
    int cols = H * Dh;
    int d = threadIdx.x * 4;
    int hh = d / Dh;
    float alpha = ex[(size_t)e * H + hh] / (den[(size_t)dst * H + hh] + 1e-16f);
    float4 v = *(const float4*)(h + (size_t)src * cols + d);
    float* o = out + (size_t)dst * cols + d;
    atomicAdd(o + 0, alpha * v.x);
    atomicAdd(o + 1, alpha * v.y);
    atomicAdd(o + 2, alpha * v.z);
    atomicAdd(o + 3, alpha * v.w);
}

__global__ void elu_bias(float* __restrict__ x, const float* __restrict__ b,
                         int n, int cols) {
    int i = blockIdx.x * blockDim.x + threadIdx.x;
    if (i >= n) return;
    float v = x[i] + b[i % cols];
    x[i] = v > 0.f ? v : expm1f(v);
}

__global__ void add_bias(float* __restrict__ x, const float* __restrict__ b,
                         int n, int cols) {
    int i = blockIdx.x * blockDim.x + threadIdx.x;
    if (i >= n) return;
    x[i] += b[i % cols];
}

// ---------------------------------------------------------------------------
extern "C" void kernel_launch(void* const* d_in, const int* in_sizes, int n_in,
                              void* d_out, int out_size) {
    const float* x   = (const float*)d_in[0];
    const int*   ei  = (const int*)d_in[1];     // int32 (JAX x64 disabled)
    const float* W1  = (const float*)d_in[2];
    const float* a1s = (const float*)d_in[3];
    const float* a1d = (const float*)d_in[4];
    const float* b1  = (const float*)d_in[5];
    const float* W2  = (const float*)d_in[6];
    const float* a2s = (const float*)d_in[7];
    const float* a2d = (const float*)d_in[8];
    const float* b2  = (const float*)d_in[9];
    float*       out = (float*)d_out;

    float *h1, *out1, *h2, *as1, *ad1, *em1, *dn1, *ex1;
    float *as2, *ad2, *em2, *dn2, *ex2;
    cudaGetSymbolAddress((void**)&h1,  g_h1);
    cudaGetSymbolAddress((void**)&out1, g_out1);
    cudaGetSymbolAddress((void**)&h2,  g_h2);
    cudaGetSymbolAddress((void**)&as1, g_as1);
    cudaGetSymbolAddress((void**)&ad1, g_ad1);
    cudaGetSymbolAddress((void**)&em1, g_emax1);
    cudaGetSymbolAddress((void**)&dn1, g_den1);
    cudaGetSymbolAddress((void**)&ex1, g_ex1);
    cudaGetSymbolAddress((void**)&as2, g_as2);
    cudaGetSymbolAddress((void**)&ad2, g_ad2);
    cudaGetSymbolAddress((void**)&em2, g_emax2);
    cudaGetSymbolAddress((void**)&dn2, g_den2);
    cudaGetSymbolAddress((void**)&ex2, g_ex2);

    cudaFuncSetAttribute(gemm_tf32x3,
                         cudaFuncAttributeMaxDynamicSharedMemorySize, GEMM_SMEM);

    // ---------------- layer 1 ----------------
    {
        dim3 grid(C1 / 128, (N_NODES + 127) / 128);
        gemm_tf32x3<<<grid, 256, GEMM_SMEM>>>(N_NODES, C1, IN_DIM, x, W1, h1);
    }
    attn_coef<<<N_NODES, 32 * HEADS>>>(h1, a1s, a1d, as1, ad1, HEADS, HID);

    int tot1 = N_NODES * HEADS;
    init_softmax<<<(tot1 + 255) / 256, 256>>>(em1, dn1, tot1);
    cudaMemsetAsync(out1, 0, sizeof(float) * (size_t)N_NODES * C1);

    int et1 = E_TOT * HEADS;
    edge_max<<<(et1 + 255) / 256, 256>>>(ei, N_EDGES, E_TOT, HEADS, as1, ad1, em1);
    edge_exp<<<(et1 + 255) / 256, 256>>>(ei, N_EDGES, E_TOT, HEADS, as1, ad1, em1, ex1, dn1);
    aggregate<<<E_TOT, C1 / 4>>>(ei, N_EDGES, h1, ex1, dn1, out1, HEADS, HID);

    int n1 = N_NODES * C1;
    elu_bias<<<(n1 + 255) / 256, 256>>>(out1, b1, n1, C1);

    // ---------------- layer 2 ----------------
    {
        dim3 grid(OUT_DIM / 128, (N_NODES + 127) / 128);
        gemm_tf32x3<<<grid, 256, GEMM_SMEM>>>(N_NODES, OUT_DIM, C1, out1, W2, h2);
    }
    attn_coef<<<N_NODES, 32>>>(h2, a2s, a2d, as2, ad2, 1, OUT_DIM);

    init_softmax<<<(N_NODES + 255) / 256, 256>>>(em2, dn2, N_NODES);
    cudaMemsetAsync(out, 0, sizeof(float) * (size_t)N_NODES * OUT_DIM);

    edge_max<<<(E_TOT + 255) / 256, 256>>>(ei, N_EDGES, E_TOT, 1, as2, ad2, em2);
    edge_exp<<<(E_TOT + 255) / 256, 256>>>(ei, N_EDGES, E_TOT, 1, as2, ad2, em2, ex2, dn2);
    aggregate<<<E_TOT, OUT_DIM / 4>>>(ei, N_EDGES, h2, ex2, dn2, out, 1, OUT_DIM);

    int n2 = N_NODES * OUT_DIM;
    add_bias<<<(n2 + 255) / 256, 256>>>(out, b2, n2, OUT_DIM);
}